// round 1
// baseline (speedup 1.0000x reference)
#include <cuda_runtime.h>
#include <cuda_bf16.h>
#include <math.h>

#define T_TOK 2048
#define HID   1024
#define DFF   2816
#define NEXP  8
#define TOPK  2

// ---------------- scratch (static device globals; no allocation) ----------------
__device__ int   g_idx[T_TOK * 2];
__device__ float g_comb[T_TOK * 2];
__device__ int   g_counts[NEXP];
__device__ int   g_offsets[NEXP];
__device__ int   g_row_token[T_TOK * 2];
__device__ float g_row_weight[T_TOK * 2];
__device__ float g_importance[NEXP];
__device__ float g_act[(size_t)T_TOK * 2 * DFF];   // 46 MB activation scratch

// ---------------- kernel 0: zero scratch ----------------
__global__ void zero_scratch_kernel() {
    int t = threadIdx.x;
    if (t < NEXP) { g_counts[t] = 0; g_importance[t] = 0.f; }
}

// ---------------- kernel 1: gating ----------------
// one block (128 thr) per token: logits[8] = x_row . gate_w[e], top2 softmax,
// full softmax for importance, atomics for counts/importance.
__global__ void gating_kernel(const float* __restrict__ x,
                              const float* __restrict__ gw) {
    int t = blockIdx.x;
    int tid = threadIdx.x;            // 128 threads
    const float* xr = x + (size_t)t * HID;

    float p[NEXP];
#pragma unroll
    for (int e = 0; e < NEXP; e++) p[e] = 0.f;

    for (int h = tid; h < HID; h += 128) {
        float xv = xr[h];
#pragma unroll
        for (int e = 0; e < NEXP; e++) p[e] += xv * gw[e * HID + h];
    }

    __shared__ float sh[NEXP][128];
#pragma unroll
    for (int e = 0; e < NEXP; e++) sh[e][tid] = p[e];
    __syncthreads();

    if (tid < NEXP) {
        float s = 0.f;
        for (int i = 0; i < 128; i++) s += sh[tid][i];
        sh[tid][0] = s;
    }
    __syncthreads();

    if (tid == 0) {
        float lg[NEXP];
#pragma unroll
        for (int e = 0; e < NEXP; e++) lg[e] = sh[e][0];

        // top-2 (earliest index wins ties, matching jax top_k)
        int i0 = 0;
#pragma unroll
        for (int e = 1; e < NEXP; e++) if (lg[e] > lg[i0]) i0 = e;
        int i1 = -1;
#pragma unroll
        for (int e = 0; e < NEXP; e++) {
            if (e == i0) continue;
            if (i1 < 0 || lg[e] > lg[i1]) i1 = e;
        }

        float m = lg[i0];
        float e1 = expf(lg[i1] - m);          // exp(v0-m)=1
        float inv = 1.f / (1.f + e1);
        g_idx[t * 2]      = i0;
        g_idx[t * 2 + 1]  = i1;
        g_comb[t * 2]     = inv;
        g_comb[t * 2 + 1] = e1 * inv;
        atomicAdd(&g_counts[i0], 1);
        atomicAdd(&g_counts[i1], 1);

        // full softmax for gate importance
        float se = 0.f, pe[NEXP];
#pragma unroll
        for (int e = 0; e < NEXP; e++) { pe[e] = expf(lg[e] - m); se += pe[e]; }
        float isum = 1.f / se;
#pragma unroll
        for (int e = 0; e < NEXP; e++) atomicAdd(&g_importance[e], pe[e] * isum);
    }
}

// ---------------- kernel 2: offsets (exclusive prefix) ----------------
__global__ void offsets_kernel() {
    if (threadIdx.x == 0) {
        int cum = 0;
        for (int e = 0; e < NEXP; e++) { g_offsets[e] = cum; cum += g_counts[e]; }
    }
}

// ---------------- kernel 3: stable per-expert compaction ----------------
__global__ void routing_kernel() {
    int e = blockIdx.x;               // one block per expert, 256 threads
    int tid = threadIdx.x;
    __shared__ int scan[256];
    __shared__ int base;
    if (tid == 0) base = g_offsets[e];
    __syncthreads();

    for (int t0 = 0; t0 < T_TOK; t0 += 256) {
        int t = t0 + tid;
        int sel = 0; float w = 0.f;
        if (g_idx[2 * t] == e)          { sel = 1; w = g_comb[2 * t]; }
        else if (g_idx[2 * t + 1] == e) { sel = 1; w = g_comb[2 * t + 1]; }
        scan[tid] = sel;
        __syncthreads();
        // Hillis-Steele inclusive scan
        for (int ofs = 1; ofs < 256; ofs <<= 1) {
            int v = 0;
            if (tid >= ofs) v = scan[tid - ofs];
            __syncthreads();
            if (tid >= ofs) scan[tid] += v;
            __syncthreads();
        }
        if (sel) {
            int pos = base + scan[tid] - 1;
            g_row_token[pos]  = t;
            g_row_weight[pos] = w;
        }
        __syncthreads();
        if (tid == 0) base += scan[255];
        __syncthreads();
    }
}

// ---------------- kernel 4: GEMM1 (gathered x @ w1 & w3 -> SwiGLU -> act) ----------------
// tiles: BM=64 BN=64 BK=16, 256 threads, 4x4 microtile, two B operands sharing A.
__global__ __launch_bounds__(256) void gemm1_kernel(const float* __restrict__ x,
                                                    const float* __restrict__ w1,
                                                    const float* __restrict__ w3) {
    const int e = blockIdx.z;
    const int count = g_counts[e];
    const int m0 = blockIdx.y * 64;
    if (m0 >= count) return;
    const int n0 = blockIdx.x * 64;
    const int off = g_offsets[e];

    const float* W1 = w1 + (size_t)e * HID * DFF;
    const float* W3 = w3 + (size_t)e * HID * DFF;

    __shared__ float As[16][64];
    __shared__ float B1s[16][64];
    __shared__ float B3s[16][64];
    __shared__ int   toks[64];

    const int tid = threadIdx.x;
    const int tx = tid % 16, ty = tid / 16;

    if (tid < 64) {
        int r = m0 + tid;
        toks[tid] = (r < count) ? g_row_token[off + r] : -1;
    }
    __syncthreads();

    float acc1[4][4], acc3[4][4];
#pragma unroll
    for (int i = 0; i < 4; i++)
#pragma unroll
        for (int j = 0; j < 4; j++) { acc1[i][j] = 0.f; acc3[i][j] = 0.f; }

    for (int k0 = 0; k0 < HID; k0 += 16) {
#pragma unroll
        for (int i = 0; i < 4; i++) {
            int idx = tid + i * 256;
            int m = idx % 64, k = idx / 64;           // k in 0..15 for i loop (idx<1024)
            int tk = toks[m];
            As[k][m] = (tk >= 0) ? x[(size_t)tk * HID + k0 + k] : 0.f;
        }
#pragma unroll
        for (int i = 0; i < 4; i++) {
            int idx = tid + i * 256;
            int n = idx % 64, k = idx / 64;
            size_t boff = (size_t)(k0 + k) * DFF + n0 + n;
            B1s[k][n] = W1[boff];
            B3s[k][n] = W3[boff];
        }
        __syncthreads();
#pragma unroll
        for (int kk = 0; kk < 16; kk++) {
            float4 a  = *(const float4*)&As[kk][ty * 4];
            float4 b1 = *(const float4*)&B1s[kk][tx * 4];
            float4 b3 = *(const float4*)&B3s[kk][tx * 4];
            float av[4] = {a.x, a.y, a.z, a.w};
            float b1v[4] = {b1.x, b1.y, b1.z, b1.w};
            float b3v[4] = {b3.x, b3.y, b3.z, b3.w};
#pragma unroll
            for (int i = 0; i < 4; i++)
#pragma unroll
                for (int j = 0; j < 4; j++) {
                    acc1[i][j] += av[i] * b1v[j];
                    acc3[i][j] += av[i] * b3v[j];
                }
        }
        __syncthreads();
    }

#pragma unroll
    for (int i = 0; i < 4; i++) {
        int m = ty * 4 + i;
        int r = m0 + m;
        if (r >= count) continue;
        float* dst = g_act + (size_t)(off + r) * DFF + n0 + tx * 4;
        float4 o;
        float h;
        h = acc1[i][0]; o.x = (h / (1.f + expf(-h))) * acc3[i][0];
        h = acc1[i][1]; o.y = (h / (1.f + expf(-h))) * acc3[i][1];
        h = acc1[i][2]; o.z = (h / (1.f + expf(-h))) * acc3[i][2];
        h = acc1[i][3]; o.w = (h / (1.f + expf(-h))) * acc3[i][3];
        *(float4*)dst = o;
    }
}

// ---------------- kernel 5: GEMM2 (act @ w2, scaled scatter-add into out) ----------------
__global__ __launch_bounds__(256) void gemm2_kernel(const float* __restrict__ w2,
                                                    float* __restrict__ out) {
    const int e = blockIdx.z;
    const int count = g_counts[e];
    const int m0 = blockIdx.y * 64;
    if (m0 >= count) return;
    const int n0 = blockIdx.x * 64;
    const int off = g_offsets[e];

    const float* W2 = w2 + (size_t)e * DFF * HID;

    __shared__ float As[16][64];
    __shared__ float Bs[16][64];
    __shared__ int   toks[64];
    __shared__ float wts[64];

    const int tid = threadIdx.x;
    const int tx = tid % 16, ty = tid / 16;

    if (tid < 64) {
        int r = m0 + tid;
        bool ok = r < count;
        toks[tid] = ok ? g_row_token[off + r] : -1;
        wts[tid]  = ok ? g_row_weight[off + r] : 0.f;
    }
    __syncthreads();

    float acc[4][4];
#pragma unroll
    for (int i = 0; i < 4; i++)
#pragma unroll
        for (int j = 0; j < 4; j++) acc[i][j] = 0.f;

    for (int k0 = 0; k0 < DFF; k0 += 16) {
#pragma unroll
        for (int i = 0; i < 4; i++) {
            int idx = tid + i * 256;
            int m = idx % 64, k = idx / 64;
            int r = m0 + m;
            As[k][m] = (r < count) ? g_act[(size_t)(off + r) * DFF + k0 + k] : 0.f;
        }
#pragma unroll
        for (int i = 0; i < 4; i++) {
            int idx = tid + i * 256;
            int n = idx % 64, k = idx / 64;
            Bs[k][n] = W2[(size_t)(k0 + k) * HID + n0 + n];
        }
        __syncthreads();
#pragma unroll
        for (int kk = 0; kk < 16; kk++) {
            float4 a = *(const float4*)&As[kk][ty * 4];
            float4 b = *(const float4*)&Bs[kk][tx * 4];
            float av[4] = {a.x, a.y, a.z, a.w};
            float bv[4] = {b.x, b.y, b.z, b.w};
#pragma unroll
            for (int i = 0; i < 4; i++)
#pragma unroll
                for (int j = 0; j < 4; j++) acc[i][j] += av[i] * bv[j];
        }
        __syncthreads();
    }

#pragma unroll
    for (int i = 0; i < 4; i++) {
        int m = ty * 4 + i;
        int r = m0 + m;
        if (r >= count) continue;
        int tk = toks[m];
        float w = wts[m];
        float* dst = out + (size_t)tk * HID + n0 + tx * 4;
#pragma unroll
        for (int j = 0; j < 4; j++) atomicAdd(&dst[j], w * acc[i][j]);
    }
}

// ---------------- kernel 6: aux loss ----------------
__global__ void aux_kernel(float* __restrict__ aux_out) {
    if (threadIdx.x == 0) {
        float s = 0.f;
        for (int e = 0; e < NEXP; e++) {
            float usage = (float)g_counts[e] / ((float)(T_TOK * TOPK) + 1e-9f);
            float imp   = g_importance[e] / (float)T_TOK;
            s += usage * imp;
        }
        float aux = s * (float)NEXP * 0.01f;
        if (aux > 1.f) aux = 1.f;
        *aux_out = aux;
    }
}

// ---------------- launch ----------------
extern "C" void kernel_launch(void* const* d_in, const int* in_sizes, int n_in,
                              void* d_out, int out_size) {
    const float* x  = (const float*)d_in[0];   // [2,1024,1024]
    const float* gw = (const float*)d_in[1];   // [8,1024]
    const float* w1 = (const float*)d_in[2];   // [8,1024,2816]
    const float* w3 = (const float*)d_in[3];   // [8,1024,2816]
    const float* w2 = (const float*)d_in[4];   // [8,2816,1024]
    float* out = (float*)d_out;

    // zero the dense output region (atomics accumulate into it)
    cudaMemsetAsync(out, 0, (size_t)T_TOK * HID * sizeof(float));

    zero_scratch_kernel<<<1, 32>>>();
    gating_kernel<<<T_TOK, 128>>>(x, gw);
    offsets_kernel<<<1, 32>>>();
    routing_kernel<<<NEXP, 256>>>();

    dim3 g1(DFF / 64, T_TOK / 64, NEXP);   // (44, 32, 8)
    gemm1_kernel<<<g1, 256>>>(x, w1, w3);

    dim3 g2(HID / 64, T_TOK / 64, NEXP);   // (16, 32, 8)
    gemm2_kernel<<<g2, 256>>>(w2, out);

    if (out_size > T_TOK * HID) {
        aux_kernel<<<1, 32>>>(out + (size_t)T_TOK * HID);
    }
}

// round 3
// speedup vs baseline: 5.1920x; 5.1920x over previous
#include <cuda_runtime.h>
#include <cstdint>
#include <math.h>

#define T_TOK 2048
#define HID   1024
#define DFF   2816
#define NEXP  8
#define TOTR  4096

// ---------------- scratch ----------------
__device__ int   g_idx[T_TOK * 2];
__device__ float g_comb[T_TOK * 2];
__device__ int   g_counts[NEXP];
__device__ int   g_offsets[NEXP];
__device__ int   g_row_token[TOTR];
__device__ float g_row_weight[TOTR];
__device__ float g_importance[NEXP];
__device__ float g_act[(size_t)TOTR * DFF];   // 46 MB

// ---------------- helpers ----------------
__device__ __forceinline__ uint32_t s2u(const void* p) {
    uint32_t a;
    asm("{ .reg .u64 t; cvta.to.shared.u64 t, %1; cvt.u32.u64 %0, t; }" : "=r"(a) : "l"(p));
    return a;
}
__device__ __forceinline__ void cp16(uint32_t s, const void* g) {
    asm volatile("cp.async.cg.shared.global [%0], [%1], 16;" :: "r"(s), "l"(g));
}
#define CP_COMMIT() asm volatile("cp.async.commit_group;" ::: "memory")
#define CP_WAIT(n)  asm volatile("cp.async.wait_group %0;" :: "n"(n) : "memory")

__device__ __forceinline__ uint32_t f2tf(float f) {
    uint32_t u;
    asm("cvt.rna.tf32.f32 %0, %1;" : "=r"(u) : "f"(f));
    return u;
}
__device__ __forceinline__ void mma8(float* d, const uint32_t* a, const uint32_t* b) {
    asm volatile(
        "mma.sync.aligned.m16n8k8.row.col.f32.tf32.tf32.f32 "
        "{%0,%1,%2,%3}, {%4,%5,%6,%7}, {%8,%9}, {%0,%1,%2,%3};"
        : "+f"(d[0]), "+f"(d[1]), "+f"(d[2]), "+f"(d[3])
        : "r"(a[0]), "r"(a[1]), "r"(a[2]), "r"(a[3]), "r"(b[0]), "r"(b[1]));
}

// smem geometry (floats)
#define A_STRIDE 20      // 16 k + 4 pad  (80B rows, 16B aligned, conflict-free frags)
#define B_STRIDE 136     // 128 n + 8 pad (544B rows, 16B aligned, conflict-free frags)
#define A_FLOATS (128 * A_STRIDE)           // 2560
#define B_FLOATS (16 * B_STRIDE)            // 2176
#define G1_STAGE_F (A_FLOATS + 2 * B_FLOATS)  // 6912 floats = 27648 B
#define G2_STAGE_F (A_FLOATS + B_FLOATS)      // 4736 floats = 18944 B
#define G1_SMEM (3 * G1_STAGE_F * 4)
#define G2_SMEM (3 * G2_STAGE_F * 4)

// ---------------- kernel 0: zero scratch ----------------
__global__ void zero_scratch_kernel() {
    int t = threadIdx.x;
    if (t < NEXP) { g_counts[t] = 0; g_importance[t] = 0.f; }
}

// ---------------- gating ----------------
__global__ void gating_kernel(const float* __restrict__ x,
                              const float* __restrict__ gw) {
    int t = blockIdx.x;
    int tid = threadIdx.x;
    const float* xr = x + (size_t)t * HID;

    float p[NEXP];
#pragma unroll
    for (int e = 0; e < NEXP; e++) p[e] = 0.f;

    for (int h = tid; h < HID; h += 128) {
        float xv = xr[h];
#pragma unroll
        for (int e = 0; e < NEXP; e++) p[e] += xv * gw[e * HID + h];
    }

    __shared__ float sh[NEXP][128];
#pragma unroll
    for (int e = 0; e < NEXP; e++) sh[e][tid] = p[e];
    __syncthreads();

    if (tid < NEXP) {
        float s = 0.f;
        for (int i = 0; i < 128; i++) s += sh[tid][i];
        sh[tid][0] = s;
    }
    __syncthreads();

    if (tid == 0) {
        float lg[NEXP];
#pragma unroll
        for (int e = 0; e < NEXP; e++) lg[e] = sh[e][0];

        int i0 = 0;
#pragma unroll
        for (int e = 1; e < NEXP; e++) if (lg[e] > lg[i0]) i0 = e;
        int i1 = -1;
#pragma unroll
        for (int e = 0; e < NEXP; e++) {
            if (e == i0) continue;
            if (i1 < 0 || lg[e] > lg[i1]) i1 = e;
        }

        float m = lg[i0];
        float e1 = expf(lg[i1] - m);
        float inv = 1.f / (1.f + e1);
        g_idx[t * 2]      = i0;
        g_idx[t * 2 + 1]  = i1;
        g_comb[t * 2]     = inv;
        g_comb[t * 2 + 1] = e1 * inv;
        atomicAdd(&g_counts[i0], 1);
        atomicAdd(&g_counts[i1], 1);

        float se = 0.f, pe[NEXP];
#pragma unroll
        for (int e = 0; e < NEXP; e++) { pe[e] = expf(lg[e] - m); se += pe[e]; }
        float isum = 1.f / se;
#pragma unroll
        for (int e = 0; e < NEXP; e++) atomicAdd(&g_importance[e], pe[e] * isum);
    }
}

// ---------------- offsets ----------------
__global__ void offsets_kernel() {
    if (threadIdx.x == 0) {
        int cum = 0;
        for (int e = 0; e < NEXP; e++) { g_offsets[e] = cum; cum += g_counts[e]; }
    }
}

// ---------------- routing ----------------
__global__ void routing_kernel() {
    int e = blockIdx.x;
    int tid = threadIdx.x;
    __shared__ int scan[256];
    __shared__ int base;
    if (tid == 0) base = g_offsets[e];
    __syncthreads();

    for (int t0 = 0; t0 < T_TOK; t0 += 256) {
        int t = t0 + tid;
        int sel = 0; float w = 0.f;
        if (g_idx[2 * t] == e)          { sel = 1; w = g_comb[2 * t]; }
        else if (g_idx[2 * t + 1] == e) { sel = 1; w = g_comb[2 * t + 1]; }
        scan[tid] = sel;
        __syncthreads();
        for (int ofs = 1; ofs < 256; ofs <<= 1) {
            int v = 0;
            if (tid >= ofs) v = scan[tid - ofs];
            __syncthreads();
            if (tid >= ofs) scan[tid] += v;
            __syncthreads();
        }
        if (sel) {
            int pos = base + scan[tid] - 1;
            g_row_token[pos]  = t;
            g_row_weight[pos] = w;
        }
        __syncthreads();
        if (tid == 0) base += scan[255];
        __syncthreads();
    }
}

// ---------------- GEMM1: X@W1 & X@W3 -> SwiGLU -> g_act (mma.sync tf32) ----------------
#define G1_KC 64   // 1024/16

__global__ __launch_bounds__(256, 1) void gemm1_mma(const float* __restrict__ x,
                                                    const float* __restrict__ w1,
                                                    const float* __restrict__ w3) {
    const int e = blockIdx.z;
    const int count = g_counts[e];
    const int m0 = blockIdx.y * 128;
    if (m0 >= count) return;
    const int n0 = blockIdx.x * 128;
    const int off = g_offsets[e];

    extern __shared__ float dsm[];
    __shared__ int toks[128];

    const int tid = threadIdx.x;
    const int wid = tid >> 5;
    const int lid = tid & 31;
    const int wm = wid >> 2;          // 0..1  (64 rows each)
    const int wn = wid & 3;           // 0..3  (32 cols each)
    const int fr = lid >> 2;          // fragment row / n-col group
    const int fc = lid & 3;           // fragment col / k group

    if (tid < 128) {
        int r = m0 + tid;
        toks[tid] = (r < count) ? g_row_token[off + r] : 0;
    }
    __syncthreads();

    const float* W1 = w1 + (size_t)e * HID * DFF + n0;
    const float* W3 = w3 + (size_t)e * HID * DFF + n0;
    const uint32_t sb = s2u(dsm);

    auto fill = [&](int chunk, int stage) {
        uint32_t base = sb + (uint32_t)stage * (G1_STAGE_F * 4);
        int k0 = chunk * 16;
#pragma unroll
        for (int j = 0; j < 2; j++) {
            int i = tid + j * 256;
            int row = i >> 2, q = i & 3;
            cp16(base + row * 80 + q * 16, x + (size_t)toks[row] * HID + k0 + q * 4);
        }
#pragma unroll
        for (int j = 0; j < 2; j++) {
            int i = tid + j * 256;
            int k = i >> 5, nq = i & 31;
            uint32_t o = k * 544 + nq * 16;
            const float* s1 = W1 + (size_t)(k0 + k) * DFF + nq * 4;
            const float* s3 = W3 + (size_t)(k0 + k) * DFF + nq * 4;
            cp16(base + A_FLOATS * 4 + o, s1);
            cp16(base + (A_FLOATS + B_FLOATS) * 4 + o, s3);
        }
        CP_COMMIT();
    };

    float acc1[4][4][4], acc3[4][4][4];
#pragma unroll
    for (int mi = 0; mi < 4; mi++)
#pragma unroll
        for (int ni = 0; ni < 4; ni++)
#pragma unroll
            for (int v = 0; v < 4; v++) { acc1[mi][ni][v] = 0.f; acc3[mi][ni][v] = 0.f; }

    fill(0, 0); fill(1, 1); fill(2, 2);

    for (int c = 0; c < G1_KC; c++) {
        if (c < G1_KC - 2)       CP_WAIT(2);
        else if (c == G1_KC - 2) CP_WAIT(1);
        else                     CP_WAIT(0);
        __syncthreads();

        const float* st = dsm + (size_t)(c % 3) * G1_STAGE_F;
        const float* As = st;
        const float* B1 = st + A_FLOATS;
        const float* B3 = st + A_FLOATS + B_FLOATS;

#pragma unroll
        for (int kk = 0; kk < 16; kk += 8) {
            uint32_t a[4][4];
#pragma unroll
            for (int mi = 0; mi < 4; mi++) {
                const float* ap = As + (wm * 64 + mi * 16 + fr) * A_STRIDE + kk + fc;
                a[mi][0] = f2tf(ap[0]);
                a[mi][1] = f2tf(ap[8 * A_STRIDE]);
                a[mi][2] = f2tf(ap[4]);
                a[mi][3] = f2tf(ap[8 * A_STRIDE + 4]);
            }
            uint32_t b1f[4][2], b3f[4][2];
#pragma unroll
            for (int ni = 0; ni < 4; ni++) {
                int n = wn * 32 + ni * 8 + fr;
                const float* bp1 = B1 + (kk + fc) * B_STRIDE + n;
                const float* bp3 = B3 + (kk + fc) * B_STRIDE + n;
                b1f[ni][0] = f2tf(bp1[0]); b1f[ni][1] = f2tf(bp1[4 * B_STRIDE]);
                b3f[ni][0] = f2tf(bp3[0]); b3f[ni][1] = f2tf(bp3[4 * B_STRIDE]);
            }
#pragma unroll
            for (int mi = 0; mi < 4; mi++)
#pragma unroll
                for (int ni = 0; ni < 4; ni++) {
                    mma8(acc1[mi][ni], a[mi], b1f[ni]);
                    mma8(acc3[mi][ni], a[mi], b3f[ni]);
                }
        }
        __syncthreads();
        if (c + 3 < G1_KC) fill(c + 3, c % 3);
    }

    // epilogue: SwiGLU, write g_act
#pragma unroll
    for (int mi = 0; mi < 4; mi++) {
        int rA = m0 + wm * 64 + mi * 16 + fr;
        int rB = rA + 8;
#pragma unroll
        for (int ni = 0; ni < 4; ni++) {
            int col = n0 + wn * 32 + ni * 8 + fc * 2;
            if (rA < count) {
                float h0 = acc1[mi][ni][0], h1 = acc1[mi][ni][1];
                float2 o;
                o.x = (h0 / (1.f + expf(-h0))) * acc3[mi][ni][0];
                o.y = (h1 / (1.f + expf(-h1))) * acc3[mi][ni][1];
                *(float2*)(g_act + (size_t)(off + rA) * DFF + col) = o;
            }
            if (rB < count) {
                float h2 = acc1[mi][ni][2], h3 = acc1[mi][ni][3];
                float2 o;
                o.x = (h2 / (1.f + expf(-h2))) * acc3[mi][ni][2];
                o.y = (h3 / (1.f + expf(-h3))) * acc3[mi][ni][3];
                *(float2*)(g_act + (size_t)(off + rB) * DFF + col) = o;
            }
        }
    }
}

// ---------------- GEMM2: act @ W2 -> weighted atomic scatter into out ----------------
#define G2_KC 176   // 2816/16

__global__ __launch_bounds__(256, 1) void gemm2_mma(const float* __restrict__ w2,
                                                    float* __restrict__ out) {
    const int e = blockIdx.z;
    const int count = g_counts[e];
    const int m0 = blockIdx.y * 128;
    if (m0 >= count) return;
    const int n0 = blockIdx.x * 128;
    const int off = g_offsets[e];

    extern __shared__ float dsm[];
    __shared__ int   toks[128];
    __shared__ float wts[128];

    const int tid = threadIdx.x;
    const int wid = tid >> 5;
    const int lid = tid & 31;
    const int wm = wid >> 2;
    const int wn = wid & 3;
    const int fr = lid >> 2;
    const int fc = lid & 3;

    if (tid < 128) {
        int r = m0 + tid;
        bool ok = r < count;
        toks[tid] = ok ? g_row_token[off + r] : 0;
        wts[tid]  = ok ? g_row_weight[off + r] : 0.f;
    }
    __syncthreads();

    const float* W2 = w2 + (size_t)e * DFF * HID + n0;
    const uint32_t sb = s2u(dsm);
    const int arow_base = off + m0;

    auto fill = [&](int chunk, int stage) {
        uint32_t base = sb + (uint32_t)stage * (G2_STAGE_F * 4);
        int k0 = chunk * 16;
#pragma unroll
        for (int j = 0; j < 2; j++) {
            int i = tid + j * 256;
            int row = i >> 2, q = i & 3;
            int ridx = arow_base + row;
            if (ridx > TOTR - 1) ridx = TOTR - 1;
            cp16(base + row * 80 + q * 16, g_act + (size_t)ridx * DFF + k0 + q * 4);
        }
#pragma unroll
        for (int j = 0; j < 2; j++) {
            int i = tid + j * 256;
            int k = i >> 5, nq = i & 31;
            cp16(base + A_FLOATS * 4 + k * 544 + nq * 16,
                 W2 + (size_t)(k0 + k) * HID + nq * 4);
        }
        CP_COMMIT();
    };

    float acc[4][4][4];
#pragma unroll
    for (int mi = 0; mi < 4; mi++)
#pragma unroll
        for (int ni = 0; ni < 4; ni++)
#pragma unroll
            for (int v = 0; v < 4; v++) acc[mi][ni][v] = 0.f;

    fill(0, 0); fill(1, 1); fill(2, 2);

    for (int c = 0; c < G2_KC; c++) {
        if (c < G2_KC - 2)       CP_WAIT(2);
        else if (c == G2_KC - 2) CP_WAIT(1);
        else                     CP_WAIT(0);
        __syncthreads();

        const float* st = dsm + (size_t)(c % 3) * G2_STAGE_F;
        const float* As = st;
        const float* Bs = st + A_FLOATS;

#pragma unroll
        for (int kk = 0; kk < 16; kk += 8) {
            uint32_t a[4][4];
#pragma unroll
            for (int mi = 0; mi < 4; mi++) {
                const float* ap = As + (wm * 64 + mi * 16 + fr) * A_STRIDE + kk + fc;
                a[mi][0] = f2tf(ap[0]);
                a[mi][1] = f2tf(ap[8 * A_STRIDE]);
                a[mi][2] = f2tf(ap[4]);
                a[mi][3] = f2tf(ap[8 * A_STRIDE + 4]);
            }
            uint32_t bf[4][2];
#pragma unroll
            for (int ni = 0; ni < 4; ni++) {
                int n = wn * 32 + ni * 8 + fr;
                const float* bp = Bs + (kk + fc) * B_STRIDE + n;
                bf[ni][0] = f2tf(bp[0]); bf[ni][1] = f2tf(bp[4 * B_STRIDE]);
            }
#pragma unroll
            for (int mi = 0; mi < 4; mi++)
#pragma unroll
                for (int ni = 0; ni < 4; ni++)
                    mma8(acc[mi][ni], a[mi], bf[ni]);
        }
        __syncthreads();
        if (c + 3 < G2_KC) fill(c + 3, c % 3);
    }

    // epilogue: weighted atomic scatter
#pragma unroll
    for (int mi = 0; mi < 4; mi++) {
        int mlA = wm * 64 + mi * 16 + fr;
        int mlB = mlA + 8;
        int rA = m0 + mlA, rB = m0 + mlB;
        int tkA = toks[mlA], tkB = toks[mlB];
        float wA = wts[mlA], wB = wts[mlB];
#pragma unroll
        for (int ni = 0; ni < 4; ni++) {
            int col = n0 + wn * 32 + ni * 8 + fc * 2;
            if (rA < count) {
                float* d = out + (size_t)tkA * HID + col;
                atomicAdd(d,     wA * acc[mi][ni][0]);
                atomicAdd(d + 1, wA * acc[mi][ni][1]);
            }
            if (rB < count) {
                float* d = out + (size_t)tkB * HID + col;
                atomicAdd(d,     wB * acc[mi][ni][2]);
                atomicAdd(d + 1, wB * acc[mi][ni][3]);
            }
        }
    }
}

// ---------------- aux loss ----------------
__global__ void aux_kernel(float* __restrict__ aux_out) {
    if (threadIdx.x == 0) {
        float s = 0.f;
        for (int e = 0; e < NEXP; e++) {
            float usage = (float)g_counts[e] / ((float)(T_TOK * 2) + 1e-9f);
            float imp   = g_importance[e] / (float)T_TOK;
            s += usage * imp;
        }
        float aux = s * (float)NEXP * 0.01f;
        if (aux > 1.f) aux = 1.f;
        *aux_out = aux;
    }
}

// ---------------- launch ----------------
extern "C" void kernel_launch(void* const* d_in, const int* in_sizes, int n_in,
                              void* d_out, int out_size) {
    const float* x  = (const float*)d_in[0];
    const float* gw = (const float*)d_in[1];
    const float* w1 = (const float*)d_in[2];
    const float* w3 = (const float*)d_in[3];
    const float* w2 = (const float*)d_in[4];
    float* out = (float*)d_out;

    cudaFuncSetAttribute(gemm1_mma, cudaFuncAttributeMaxDynamicSharedMemorySize, G1_SMEM);
    cudaFuncSetAttribute(gemm2_mma, cudaFuncAttributeMaxDynamicSharedMemorySize, G2_SMEM);

    cudaMemsetAsync(out, 0, (size_t)T_TOK * HID * sizeof(float));

    zero_scratch_kernel<<<1, 32>>>();
    gating_kernel<<<T_TOK, 128>>>(x, gw);
    offsets_kernel<<<1, 32>>>();
    routing_kernel<<<NEXP, 256>>>();

    dim3 g1(DFF / 128, T_TOK / 128, NEXP);   // (22, 16, 8)
    gemm1_mma<<<g1, 256, G1_SMEM>>>(x, w1, w3);

    dim3 g2(HID / 128, T_TOK / 128, NEXP);   // (8, 16, 8)
    gemm2_mma<<<g2, 256, G2_SMEM>>>(w2, out);

    if (out_size > T_TOK * HID) {
        aux_kernel<<<1, 32>>>(out + (size_t)T_TOK * HID);
    }
}

// round 4
// speedup vs baseline: 7.6429x; 1.4720x over previous
#include <cuda_runtime.h>
#include <cuda_fp16.h>
#include <cstdint>
#include <math.h>

#define T_TOK 2048
#define HID   1024
#define DFF   2816
#define NEXP  8
#define TOTR  4096

// ---------------- scratch ----------------
__device__ int    g_idx[T_TOK * 2];
__device__ float  g_comb[T_TOK * 2];
__device__ int    g_counts[NEXP];
__device__ int    g_offsets[NEXP];
__device__ int    g_row_token[TOTR];
__device__ float  g_row_weight[TOTR];
__device__ float  g_importance[NEXP];
__device__ __half g_xh[(size_t)T_TOK * HID];                    // 4 MB
__device__ __half g_acth[(size_t)TOTR * DFF];                   // 23 MB
__device__ __half g_w1h[(size_t)NEXP * HID * DFF];              // 46 MB [E][K=H][N=F]
__device__ __half g_w3h[(size_t)NEXP * HID * DFF];              // 46 MB
__device__ __half g_w2h[(size_t)NEXP * DFF * HID];              // 46 MB [E][K=F][N=H]

// ---------------- helpers ----------------
__device__ __forceinline__ uint32_t s2u(const void* p) {
    uint32_t a;
    asm("{ .reg .u64 t; cvta.to.shared.u64 t, %1; cvt.u32.u64 %0, t; }" : "=r"(a) : "l"(p));
    return a;
}
__device__ __forceinline__ void cp16(uint32_t s, const void* g) {
    asm volatile("cp.async.cg.shared.global [%0], [%1], 16;" :: "r"(s), "l"(g));
}
#define CP_COMMIT() asm volatile("cp.async.commit_group;" ::: "memory")
#define CP_WAIT(n)  asm volatile("cp.async.wait_group %0;" :: "n"(n) : "memory")

__device__ __forceinline__ void ldsm4(uint32_t* r, uint32_t a) {
    asm volatile("ldmatrix.sync.aligned.m8n8.x4.shared.b16 {%0,%1,%2,%3}, [%4];"
                 : "=r"(r[0]), "=r"(r[1]), "=r"(r[2]), "=r"(r[3]) : "r"(a));
}
__device__ __forceinline__ void ldsm4t(uint32_t* r, uint32_t a) {
    asm volatile("ldmatrix.sync.aligned.m8n8.x4.trans.shared.b16 {%0,%1,%2,%3}, [%4];"
                 : "=r"(r[0]), "=r"(r[1]), "=r"(r[2]), "=r"(r[3]) : "r"(a));
}
__device__ __forceinline__ void mma16(float* d, const uint32_t* a, const uint32_t* b) {
    asm volatile(
        "mma.sync.aligned.m16n8k16.row.col.f32.f16.f16.f32 "
        "{%0,%1,%2,%3}, {%4,%5,%6,%7}, {%8,%9}, {%0,%1,%2,%3};"
        : "+f"(d[0]), "+f"(d[1]), "+f"(d[2]), "+f"(d[3])
        : "r"(a[0]), "r"(a[1]), "r"(a[2]), "r"(a[3]), "r"(b[0]), "r"(b[1]));
}

// smem geometry (halves)
#define AH_STRIDE 40          // 32 k + 8 pad (80 B rows; mod-32-word conflict-free)
#define BH_STRIDE 136         // 128 n + 8 pad (272 B rows; conflict-free)
#define A_HALVES (128 * AH_STRIDE)     // 5120 halves = 10240 B
#define B_HALVES (32 * BH_STRIDE)      // 4352 halves = 8704 B
#define G1_STG_B (A_HALVES * 2 + B_HALVES * 2 * 2)   // 27648 B
#define G2_STG_B (A_HALVES * 2 + B_HALVES * 2)       // 18944 B
#define G1_SMEM (3 * G1_STG_B)
#define G2_SMEM (3 * G2_STG_B)

// ---------------- fp32 -> fp16 convert ----------------
__global__ void cvt_fp16(const float4* __restrict__ src, __half2* __restrict__ dst, int n4) {
    int i = blockIdx.x * blockDim.x + threadIdx.x;
    if (i < n4) {
        float4 v = src[i];
        dst[2 * i]     = __floats2half2_rn(v.x, v.y);
        dst[2 * i + 1] = __floats2half2_rn(v.z, v.w);
    }
}

// ---------------- zero / gating / offsets / routing ----------------
__global__ void zero_scratch_kernel() {
    int t = threadIdx.x;
    if (t < NEXP) { g_counts[t] = 0; g_importance[t] = 0.f; }
}

__global__ void gating_kernel(const float* __restrict__ x,
                              const float* __restrict__ gw) {
    int t = blockIdx.x;
    int tid = threadIdx.x;
    const float* xr = x + (size_t)t * HID;

    float p[NEXP];
#pragma unroll
    for (int e = 0; e < NEXP; e++) p[e] = 0.f;
    for (int h = tid; h < HID; h += 128) {
        float xv = xr[h];
#pragma unroll
        for (int e = 0; e < NEXP; e++) p[e] += xv * gw[e * HID + h];
    }

    __shared__ float sh[NEXP][128];
#pragma unroll
    for (int e = 0; e < NEXP; e++) sh[e][tid] = p[e];
    __syncthreads();
    if (tid < NEXP) {
        float s = 0.f;
        for (int i = 0; i < 128; i++) s += sh[tid][i];
        sh[tid][0] = s;
    }
    __syncthreads();

    if (tid == 0) {
        float lg[NEXP];
#pragma unroll
        for (int e = 0; e < NEXP; e++) lg[e] = sh[e][0];
        int i0 = 0;
#pragma unroll
        for (int e = 1; e < NEXP; e++) if (lg[e] > lg[i0]) i0 = e;
        int i1 = -1;
#pragma unroll
        for (int e = 0; e < NEXP; e++) {
            if (e == i0) continue;
            if (i1 < 0 || lg[e] > lg[i1]) i1 = e;
        }
        float m = lg[i0];
        float e1 = expf(lg[i1] - m);
        float inv = 1.f / (1.f + e1);
        g_idx[t * 2]      = i0;
        g_idx[t * 2 + 1]  = i1;
        g_comb[t * 2]     = inv;
        g_comb[t * 2 + 1] = e1 * inv;
        atomicAdd(&g_counts[i0], 1);
        atomicAdd(&g_counts[i1], 1);

        float se = 0.f, pe[NEXP];
#pragma unroll
        for (int e = 0; e < NEXP; e++) { pe[e] = expf(lg[e] - m); se += pe[e]; }
        float isum = 1.f / se;
#pragma unroll
        for (int e = 0; e < NEXP; e++) atomicAdd(&g_importance[e], pe[e] * isum);
    }
}

__global__ void offsets_kernel() {
    if (threadIdx.x == 0) {
        int cum = 0;
        for (int e = 0; e < NEXP; e++) { g_offsets[e] = cum; cum += g_counts[e]; }
    }
}

__global__ void routing_kernel() {
    int e = blockIdx.x;
    int tid = threadIdx.x;
    __shared__ int scan[256];
    __shared__ int base;
    if (tid == 0) base = g_offsets[e];
    __syncthreads();

    for (int t0 = 0; t0 < T_TOK; t0 += 256) {
        int t = t0 + tid;
        int sel = 0; float w = 0.f;
        if (g_idx[2 * t] == e)          { sel = 1; w = g_comb[2 * t]; }
        else if (g_idx[2 * t + 1] == e) { sel = 1; w = g_comb[2 * t + 1]; }
        scan[tid] = sel;
        __syncthreads();
        for (int ofs = 1; ofs < 256; ofs <<= 1) {
            int v = 0;
            if (tid >= ofs) v = scan[tid - ofs];
            __syncthreads();
            if (tid >= ofs) scan[tid] += v;
            __syncthreads();
        }
        if (sel) {
            int pos = base + scan[tid] - 1;
            g_row_token[pos]  = t;
            g_row_weight[pos] = w;
        }
        __syncthreads();
        if (tid == 0) base += scan[255];
        __syncthreads();
    }
}

// ---------------- GEMM1: Xh@W1h & Xh@W3h -> SwiGLU -> g_acth ----------------
#define G1_KC 32   // 1024/32

__global__ __launch_bounds__(256) void gemm1_mma(const __half* __restrict__ xh,
                                                 const __half* __restrict__ w1h,
                                                 const __half* __restrict__ w3h) {
    const int e = blockIdx.z;
    const int count = g_counts[e];
    const int m0 = blockIdx.y * 128;
    if (m0 >= count) return;
    const int n0 = blockIdx.x * 128;
    const int off = g_offsets[e];

    extern __shared__ __half dsm[];
    __shared__ int toks[128];

    const int tid = threadIdx.x;
    const int wid = tid >> 5;
    const int lid = tid & 31;
    const int wm = wid >> 2;          // 0..1
    const int wn = wid & 3;           // 0..3
    const int fr = lid >> 2;
    const int fc = lid & 3;
    const int l8 = lid & 7;
    const int s1 = (lid >> 3) & 1;
    const int s2 = (lid >> 4) & 1;

    if (tid < 128) {
        int r = m0 + tid;
        toks[tid] = (r < count) ? g_row_token[off + r] : 0;
    }
    __syncthreads();

    const __half* W1 = w1h + (size_t)e * HID * DFF + n0;
    const __half* W3 = w3h + (size_t)e * HID * DFF + n0;
    const uint32_t sb = s2u(dsm);

    // ldmatrix per-lane offsets (bytes)
    const uint32_t a_lane = (uint32_t)(((l8 + s1 * 8) * AH_STRIDE + s2 * 8) * 2);
    const uint32_t b_lane = (uint32_t)(((s1 * 8 + l8) * BH_STRIDE + s2 * 8) * 2);

    auto fill = [&](int chunk, int stage) {
        uint32_t base = sb + (uint32_t)stage * G1_STG_B;
        int k0 = chunk * 32;
#pragma unroll
        for (int j = 0; j < 2; j++) {
            int i = tid + j * 256;
            int row = i >> 2, q = i & 3;
            cp16(base + (uint32_t)(row * AH_STRIDE + q * 8) * 2,
                 xh + (size_t)toks[row] * HID + k0 + q * 8);
        }
        uint32_t bb = base + A_HALVES * 2;
#pragma unroll
        for (int j = 0; j < 2; j++) {
            int i = tid + j * 256;
            int k = i >> 4, q = i & 15;
            uint32_t o = (uint32_t)(k * BH_STRIDE + q * 8) * 2;
            cp16(bb + o,                W1 + (size_t)(k0 + k) * DFF + q * 8);
            cp16(bb + B_HALVES * 2 + o, W3 + (size_t)(k0 + k) * DFF + q * 8);
        }
        CP_COMMIT();
    };

    float acc1[4][4][4], acc3[4][4][4];
#pragma unroll
    for (int mi = 0; mi < 4; mi++)
#pragma unroll
        for (int ni = 0; ni < 4; ni++)
#pragma unroll
            for (int v = 0; v < 4; v++) { acc1[mi][ni][v] = 0.f; acc3[mi][ni][v] = 0.f; }

    fill(0, 0); fill(1, 1); fill(2, 2);

    for (int c = 0; c < G1_KC; c++) {
        if (c < G1_KC - 2)       CP_WAIT(2);
        else if (c == G1_KC - 2) CP_WAIT(1);
        else                     CP_WAIT(0);
        __syncthreads();

        uint32_t stA  = sb + (uint32_t)(c % 3) * G1_STG_B;
        uint32_t stB1 = stA + A_HALVES * 2;
        uint32_t stB3 = stB1 + B_HALVES * 2;

#pragma unroll
        for (int ks = 0; ks < 2; ks++) {
            int kk = ks * 16;
            uint32_t afr[4][4];
#pragma unroll
            for (int mi = 0; mi < 4; mi++)
                ldsm4(afr[mi], stA + (uint32_t)((wm * 64 + mi * 16) * AH_STRIDE + kk) * 2 + a_lane);
            uint32_t b1f[2][4], b3f[2][4];
#pragma unroll
            for (int np = 0; np < 2; np++) {
                uint32_t ba = (uint32_t)(kk * BH_STRIDE + wn * 32 + np * 16) * 2 + b_lane;
                ldsm4t(b1f[np], stB1 + ba);
                ldsm4t(b3f[np], stB3 + ba);
            }
#pragma unroll
            for (int mi = 0; mi < 4; mi++)
#pragma unroll
                for (int np = 0; np < 2; np++) {
                    mma16(acc1[mi][np * 2],     afr[mi], &b1f[np][0]);
                    mma16(acc1[mi][np * 2 + 1], afr[mi], &b1f[np][2]);
                    mma16(acc3[mi][np * 2],     afr[mi], &b3f[np][0]);
                    mma16(acc3[mi][np * 2 + 1], afr[mi], &b3f[np][2]);
                }
        }
        __syncthreads();
        if (c + 3 < G1_KC) fill(c + 3, c % 3);
    }

    // epilogue: SwiGLU -> fp16 act
#pragma unroll
    for (int mi = 0; mi < 4; mi++) {
        int rA = m0 + wm * 64 + mi * 16 + fr;
        int rB = rA + 8;
#pragma unroll
        for (int ni = 0; ni < 4; ni++) {
            int col = n0 + wn * 32 + ni * 8 + fc * 2;
            if (rA < count) {
                float h0 = acc1[mi][ni][0], h1 = acc1[mi][ni][1];
                float ox = (h0 / (1.f + expf(-h0))) * acc3[mi][ni][0];
                float oy = (h1 / (1.f + expf(-h1))) * acc3[mi][ni][1];
                *(__half2*)(g_acth + (size_t)(off + rA) * DFF + col) = __floats2half2_rn(ox, oy);
            }
            if (rB < count) {
                float h2 = acc1[mi][ni][2], h3 = acc1[mi][ni][3];
                float ox = (h2 / (1.f + expf(-h2))) * acc3[mi][ni][2];
                float oy = (h3 / (1.f + expf(-h3))) * acc3[mi][ni][3];
                *(__half2*)(g_acth + (size_t)(off + rB) * DFF + col) = __floats2half2_rn(ox, oy);
            }
        }
    }
}

// ---------------- GEMM2: acth @ W2h -> weighted atomic scatter ----------------
#define G2_KC 88   // 2816/32

__global__ __launch_bounds__(256) void gemm2_mma(const __half* __restrict__ w2h,
                                                 float* __restrict__ out) {
    const int e = blockIdx.z;
    const int count = g_counts[e];
    const int m0 = blockIdx.y * 128;
    if (m0 >= count) return;
    const int n0 = blockIdx.x * 128;
    const int off = g_offsets[e];

    extern __shared__ __half dsm[];
    __shared__ int   toks[128];
    __shared__ float wts[128];

    const int tid = threadIdx.x;
    const int wid = tid >> 5;
    const int lid = tid & 31;
    const int wm = wid >> 2;
    const int wn = wid & 3;
    const int fr = lid >> 2;
    const int fc = lid & 3;
    const int l8 = lid & 7;
    const int s1 = (lid >> 3) & 1;
    const int s2 = (lid >> 4) & 1;

    if (tid < 128) {
        int r = m0 + tid;
        bool ok = r < count;
        toks[tid] = ok ? g_row_token[off + r] : 0;
        wts[tid]  = ok ? g_row_weight[off + r] : 0.f;
    }
    __syncthreads();

    const __half* W2 = w2h + (size_t)e * DFF * HID + n0;
    const uint32_t sb = s2u(dsm);
    const int arow_base = off + m0;

    const uint32_t a_lane = (uint32_t)(((l8 + s1 * 8) * AH_STRIDE + s2 * 8) * 2);
    const uint32_t b_lane = (uint32_t)(((s1 * 8 + l8) * BH_STRIDE + s2 * 8) * 2);

    auto fill = [&](int chunk, int stage) {
        uint32_t base = sb + (uint32_t)stage * G2_STG_B;
        int k0 = chunk * 32;
#pragma unroll
        for (int j = 0; j < 2; j++) {
            int i = tid + j * 256;
            int row = i >> 2, q = i & 3;
            int ridx = arow_base + row;
            if (ridx > TOTR - 1) ridx = TOTR - 1;
            cp16(base + (uint32_t)(row * AH_STRIDE + q * 8) * 2,
                 g_acth + (size_t)ridx * DFF + k0 + q * 8);
        }
        uint32_t bb = base + A_HALVES * 2;
#pragma unroll
        for (int j = 0; j < 2; j++) {
            int i = tid + j * 256;
            int k = i >> 4, q = i & 15;
            cp16(bb + (uint32_t)(k * BH_STRIDE + q * 8) * 2,
                 W2 + (size_t)(k0 + k) * HID + q * 8);
        }
        CP_COMMIT();
    };

    float acc[4][4][4];
#pragma unroll
    for (int mi = 0; mi < 4; mi++)
#pragma unroll
        for (int ni = 0; ni < 4; ni++)
#pragma unroll
            for (int v = 0; v < 4; v++) acc[mi][ni][v] = 0.f;

    fill(0, 0); fill(1, 1); fill(2, 2);

    for (int c = 0; c < G2_KC; c++) {
        if (c < G2_KC - 2)       CP_WAIT(2);
        else if (c == G2_KC - 2) CP_WAIT(1);
        else                     CP_WAIT(0);
        __syncthreads();

        uint32_t stA = sb + (uint32_t)(c % 3) * G2_STG_B;
        uint32_t stB = stA + A_HALVES * 2;

#pragma unroll
        for (int ks = 0; ks < 2; ks++) {
            int kk = ks * 16;
            uint32_t afr[4][4];
#pragma unroll
            for (int mi = 0; mi < 4; mi++)
                ldsm4(afr[mi], stA + (uint32_t)((wm * 64 + mi * 16) * AH_STRIDE + kk) * 2 + a_lane);
            uint32_t bf[2][4];
#pragma unroll
            for (int np = 0; np < 2; np++)
                ldsm4t(bf[np], stB + (uint32_t)(kk * BH_STRIDE + wn * 32 + np * 16) * 2 + b_lane);
#pragma unroll
            for (int mi = 0; mi < 4; mi++)
#pragma unroll
                for (int np = 0; np < 2; np++) {
                    mma16(acc[mi][np * 2],     afr[mi], &bf[np][0]);
                    mma16(acc[mi][np * 2 + 1], afr[mi], &bf[np][2]);
                }
        }
        __syncthreads();
        if (c + 3 < G2_KC) fill(c + 3, c % 3);
    }

#pragma unroll
    for (int mi = 0; mi < 4; mi++) {
        int mlA = wm * 64 + mi * 16 + fr;
        int mlB = mlA + 8;
        int rA = m0 + mlA, rB = m0 + mlB;
        int tkA = toks[mlA], tkB = toks[mlB];
        float wA = wts[mlA], wB = wts[mlB];
#pragma unroll
        for (int ni = 0; ni < 4; ni++) {
            int col = n0 + wn * 32 + ni * 8 + fc * 2;
            if (rA < count) {
                float* d = out + (size_t)tkA * HID + col;
                atomicAdd(d,     wA * acc[mi][ni][0]);
                atomicAdd(d + 1, wA * acc[mi][ni][1]);
            }
            if (rB < count) {
                float* d = out + (size_t)tkB * HID + col;
                atomicAdd(d,     wB * acc[mi][ni][2]);
                atomicAdd(d + 1, wB * acc[mi][ni][3]);
            }
        }
    }
}

// ---------------- aux loss ----------------
__global__ void aux_kernel(float* __restrict__ aux_out) {
    if (threadIdx.x == 0) {
        float s = 0.f;
        for (int e = 0; e < NEXP; e++) {
            float usage = (float)g_counts[e] / ((float)(T_TOK * 2) + 1e-9f);
            float imp   = g_importance[e] / (float)T_TOK;
            s += usage * imp;
        }
        float aux = s * (float)NEXP * 0.01f;
        if (aux > 1.f) aux = 1.f;
        *aux_out = aux;
    }
}

// ---------------- launch ----------------
extern "C" void kernel_launch(void* const* d_in, const int* in_sizes, int n_in,
                              void* d_out, int out_size) {
    const float* x  = (const float*)d_in[0];
    const float* gw = (const float*)d_in[1];
    const float* w1 = (const float*)d_in[2];
    const float* w3 = (const float*)d_in[3];
    const float* w2 = (const float*)d_in[4];
    float* out = (float*)d_out;

    void *p_xh, *p_w1h, *p_w3h, *p_w2h;
    cudaGetSymbolAddress(&p_xh,  g_xh);
    cudaGetSymbolAddress(&p_w1h, g_w1h);
    cudaGetSymbolAddress(&p_w3h, g_w3h);
    cudaGetSymbolAddress(&p_w2h, g_w2h);

    cudaFuncSetAttribute(gemm1_mma, cudaFuncAttributeMaxDynamicSharedMemorySize, G1_SMEM + 1024);
    cudaFuncSetAttribute(gemm2_mma, cudaFuncAttributeMaxDynamicSharedMemorySize, G2_SMEM + 1024);

    cudaMemsetAsync(out, 0, (size_t)T_TOK * HID * sizeof(float));

    // fp32 -> fp16 conversion passes
    {
        int n4x = T_TOK * HID / 4;
        cvt_fp16<<<(n4x + 255) / 256, 256>>>((const float4*)x, (__half2*)p_xh, n4x);
        int n4w = NEXP * HID * DFF / 4;
        cvt_fp16<<<(n4w + 255) / 256, 256>>>((const float4*)w1, (__half2*)p_w1h, n4w);
        cvt_fp16<<<(n4w + 255) / 256, 256>>>((const float4*)w3, (__half2*)p_w3h, n4w);
        cvt_fp16<<<(n4w + 255) / 256, 256>>>((const float4*)w2, (__half2*)p_w2h, n4w);
    }

    zero_scratch_kernel<<<1, 32>>>();
    gating_kernel<<<T_TOK, 128>>>(x, gw);
    offsets_kernel<<<1, 32>>>();
    routing_kernel<<<NEXP, 256>>>();

    dim3 g1(DFF / 128, T_TOK / 128, NEXP);   // (22, 16, 8)
    gemm1_mma<<<g1, 256, G1_SMEM + 1024>>>((const __half*)p_xh, (const __half*)p_w1h, (const __half*)p_w3h);

    dim3 g2(HID / 128, T_TOK / 128, NEXP);   // (8, 16, 8)
    gemm2_mma<<<g2, 256, G2_SMEM + 1024>>>((const __half*)p_w2h, out);

    if (out_size > T_TOK * HID) {
        aux_kernel<<<1, 32>>>(out + (size_t)T_TOK * HID);
    }
}

// round 5
// speedup vs baseline: 7.6885x; 1.0060x over previous
#include <cuda_runtime.h>
#include <cuda_fp16.h>
#include <cstdint>
#include <math.h>

#define T_TOK 2048
#define HID   1024
#define DFF   2816
#define NEXP  8
#define TOTR  4096

// ---------------- scratch ----------------
__device__ int    g_idx[T_TOK * 2];
__device__ float  g_comb[T_TOK * 2];
__device__ int    g_counts[NEXP];
__device__ int    g_offsets[NEXP];
__device__ int    g_row_token[TOTR];
__device__ float  g_row_weight[TOTR];
__device__ float  g_importance[NEXP];
__device__ __half g_xh[(size_t)T_TOK * HID];                    // 4 MB
__device__ __half g_acth[(size_t)TOTR * DFF];                   // 23 MB
__device__ __half g_w1h[(size_t)NEXP * HID * DFF];              // 46 MB [E][K=H][N=F]
__device__ __half g_w3h[(size_t)NEXP * HID * DFF];              // 46 MB
__device__ __half g_w2h[(size_t)NEXP * DFF * HID];              // 46 MB [E][K=F][N=H]

// ---------------- helpers ----------------
__device__ __forceinline__ uint32_t s2u(const void* p) {
    uint32_t a;
    asm("{ .reg .u64 t; cvta.to.shared.u64 t, %1; cvt.u32.u64 %0, t; }" : "=r"(a) : "l"(p));
    return a;
}
__device__ __forceinline__ void cp16(uint32_t s, const void* g) {
    asm volatile("cp.async.cg.shared.global [%0], [%1], 16;" :: "r"(s), "l"(g));
}
#define CP_COMMIT() asm volatile("cp.async.commit_group;" ::: "memory")
#define CP_WAIT(n)  asm volatile("cp.async.wait_group %0;" :: "n"(n) : "memory")

__device__ __forceinline__ void ldsm4(uint32_t* r, uint32_t a) {
    asm volatile("ldmatrix.sync.aligned.m8n8.x4.shared.b16 {%0,%1,%2,%3}, [%4];"
                 : "=r"(r[0]), "=r"(r[1]), "=r"(r[2]), "=r"(r[3]) : "r"(a));
}
__device__ __forceinline__ void ldsm4t(uint32_t* r, uint32_t a) {
    asm volatile("ldmatrix.sync.aligned.m8n8.x4.trans.shared.b16 {%0,%1,%2,%3}, [%4];"
                 : "=r"(r[0]), "=r"(r[1]), "=r"(r[2]), "=r"(r[3]) : "r"(a));
}
__device__ __forceinline__ void mma16(float* d, const uint32_t* a, const uint32_t* b) {
    asm volatile(
        "mma.sync.aligned.m16n8k16.row.col.f32.f16.f16.f32 "
        "{%0,%1,%2,%3}, {%4,%5,%6,%7}, {%8,%9}, {%0,%1,%2,%3};"
        : "+f"(d[0]), "+f"(d[1]), "+f"(d[2]), "+f"(d[3])
        : "r"(a[0]), "r"(a[1]), "r"(a[2]), "r"(a[3]), "r"(b[0]), "r"(b[1]));
}

// smem geometry (halves)
#define AH_STRIDE 40          // 32 k + 8 pad
#define BH_STRIDE 136         // 128 n + 8 pad
#define A_HALVES (128 * AH_STRIDE)     // 5120 halves = 10240 B
#define B_HALVES (32 * BH_STRIDE)      // 4352 halves = 8704 B
#define G1_STG_B (A_HALVES * 2 + B_HALVES * 2 * 2)   // 27648 B
#define G2_STG_B (A_HALVES * 2 + B_HALVES * 2)       // 18944 B
#define NSTAGE 4
#define G1_SMEM (NSTAGE * G1_STG_B)   // 110592 B
#define G2_SMEM (NSTAGE * G2_STG_B)   // 75776 B

// ---------------- fp32 -> fp16 convert ----------------
__global__ void cvt_fp16(const float4* __restrict__ src, __half2* __restrict__ dst, int n4) {
    int i = blockIdx.x * blockDim.x + threadIdx.x;
    if (i < n4) {
        float4 v = src[i];
        dst[2 * i]     = __floats2half2_rn(v.x, v.y);
        dst[2 * i + 1] = __floats2half2_rn(v.z, v.w);
    }
}

// ---------------- zero / gating / offsets / routing ----------------
__global__ void zero_scratch_kernel() {
    int t = threadIdx.x;
    if (t < NEXP) { g_counts[t] = 0; g_importance[t] = 0.f; }
}

__global__ void gating_kernel(const float* __restrict__ x,
                              const float* __restrict__ gw) {
    int t = blockIdx.x;
    int tid = threadIdx.x;
    const float* xr = x + (size_t)t * HID;

    float p[NEXP];
#pragma unroll
    for (int e = 0; e < NEXP; e++) p[e] = 0.f;
    for (int h = tid; h < HID; h += 128) {
        float xv = xr[h];
#pragma unroll
        for (int e = 0; e < NEXP; e++) p[e] += xv * gw[e * HID + h];
    }

    __shared__ float sh[NEXP][128];
#pragma unroll
    for (int e = 0; e < NEXP; e++) sh[e][tid] = p[e];
    __syncthreads();
    if (tid < NEXP) {
        float s = 0.f;
        for (int i = 0; i < 128; i++) s += sh[tid][i];
        sh[tid][0] = s;
    }
    __syncthreads();

    if (tid == 0) {
        float lg[NEXP];
#pragma unroll
        for (int e = 0; e < NEXP; e++) lg[e] = sh[e][0];
        int i0 = 0;
#pragma unroll
        for (int e = 1; e < NEXP; e++) if (lg[e] > lg[i0]) i0 = e;
        int i1 = -1;
#pragma unroll
        for (int e = 0; e < NEXP; e++) {
            if (e == i0) continue;
            if (i1 < 0 || lg[e] > lg[i1]) i1 = e;
        }
        float m = lg[i0];
        float e1 = expf(lg[i1] - m);
        float inv = 1.f / (1.f + e1);
        g_idx[t * 2]      = i0;
        g_idx[t * 2 + 1]  = i1;
        g_comb[t * 2]     = inv;
        g_comb[t * 2 + 1] = e1 * inv;
        atomicAdd(&g_counts[i0], 1);
        atomicAdd(&g_counts[i1], 1);

        float se = 0.f, pe[NEXP];
#pragma unroll
        for (int e = 0; e < NEXP; e++) { pe[e] = expf(lg[e] - m); se += pe[e]; }
        float isum = 1.f / se;
#pragma unroll
        for (int e = 0; e < NEXP; e++) atomicAdd(&g_importance[e], pe[e] * isum);
    }
}

__global__ void offsets_kernel() {
    if (threadIdx.x == 0) {
        int cum = 0;
        for (int e = 0; e < NEXP; e++) { g_offsets[e] = cum; cum += g_counts[e]; }
    }
}

__global__ void routing_kernel() {
    int e = blockIdx.x;
    int tid = threadIdx.x;
    __shared__ int scan[256];
    __shared__ int base;
    if (tid == 0) base = g_offsets[e];
    __syncthreads();

    for (int t0 = 0; t0 < T_TOK; t0 += 256) {
        int t = t0 + tid;
        int sel = 0; float w = 0.f;
        if (g_idx[2 * t] == e)          { sel = 1; w = g_comb[2 * t]; }
        else if (g_idx[2 * t + 1] == e) { sel = 1; w = g_comb[2 * t + 1]; }
        scan[tid] = sel;
        __syncthreads();
        for (int ofs = 1; ofs < 256; ofs <<= 1) {
            int v = 0;
            if (tid >= ofs) v = scan[tid - ofs];
            __syncthreads();
            if (tid >= ofs) scan[tid] += v;
            __syncthreads();
        }
        if (sel) {
            int pos = base + scan[tid] - 1;
            g_row_token[pos]  = t;
            g_row_weight[pos] = w;
        }
        __syncthreads();
        if (tid == 0) base += scan[255];
        __syncthreads();
    }
}

// ---------------- GEMM1: Xh@W1h & Xh@W3h -> SwiGLU -> g_acth ----------------
#define G1_KC 32   // 1024/32

__global__ __launch_bounds__(256) void gemm1_mma(const __half* __restrict__ xh,
                                                 const __half* __restrict__ w1h,
                                                 const __half* __restrict__ w3h) {
    const int e = blockIdx.z;
    const int count = g_counts[e];
    const int m0 = blockIdx.y * 128;
    if (m0 >= count) return;
    const int n0 = blockIdx.x * 128;
    const int off = g_offsets[e];

    extern __shared__ __half dsm[];
    __shared__ int toks[128];

    const int tid = threadIdx.x;
    const int wid = tid >> 5;
    const int lid = tid & 31;
    const int wm = wid >> 2;          // 0..1
    const int wn = wid & 3;           // 0..3
    const int fr = lid >> 2;
    const int fc = lid & 3;
    const int l8 = lid & 7;
    const int s1 = (lid >> 3) & 1;
    const int s2 = (lid >> 4) & 1;

    if (tid < 128) {
        int r = m0 + tid;
        toks[tid] = (r < count) ? g_row_token[off + r] : 0;
    }
    __syncthreads();

    const __half* W1 = w1h + (size_t)e * HID * DFF + n0;
    const __half* W3 = w3h + (size_t)e * HID * DFF + n0;
    const uint32_t sb = s2u(dsm);

    const uint32_t a_lane = (uint32_t)(((l8 + s1 * 8) * AH_STRIDE + s2 * 8) * 2);
    const uint32_t b_lane = (uint32_t)(((s1 * 8 + l8) * BH_STRIDE + s2 * 8) * 2);

    auto fill = [&](int chunk, int stage) {
        uint32_t base = sb + (uint32_t)stage * G1_STG_B;
        int k0 = chunk * 32;
#pragma unroll
        for (int j = 0; j < 2; j++) {
            int i = tid + j * 256;
            int row = i >> 2, q = i & 3;
            cp16(base + (uint32_t)(row * AH_STRIDE + q * 8) * 2,
                 xh + (size_t)toks[row] * HID + k0 + q * 8);
        }
        uint32_t bb = base + A_HALVES * 2;
#pragma unroll
        for (int j = 0; j < 2; j++) {
            int i = tid + j * 256;
            int k = i >> 4, q = i & 15;
            uint32_t o = (uint32_t)(k * BH_STRIDE + q * 8) * 2;
            cp16(bb + o,                W1 + (size_t)(k0 + k) * DFF + q * 8);
            cp16(bb + B_HALVES * 2 + o, W3 + (size_t)(k0 + k) * DFF + q * 8);
        }
        CP_COMMIT();
    };

    float acc1[4][4][4], acc3[4][4][4];
#pragma unroll
    for (int mi = 0; mi < 4; mi++)
#pragma unroll
        for (int ni = 0; ni < 4; ni++)
#pragma unroll
            for (int v = 0; v < 4; v++) { acc1[mi][ni][v] = 0.f; acc3[mi][ni][v] = 0.f; }

    fill(0, 0); fill(1, 1); fill(2, 2);

    for (int c = 0; c < G1_KC; c++) {
        if (c < G1_KC - 2)       CP_WAIT(2);
        else if (c == G1_KC - 2) CP_WAIT(1);
        else                     CP_WAIT(0);
        __syncthreads();                 // also protects slot (c+3)&3 (consumed at c-1)
        if (c + 3 < G1_KC) fill(c + 3, (c + 3) & 3);

        uint32_t stA  = sb + (uint32_t)(c & 3) * G1_STG_B;
        uint32_t stB1 = stA + A_HALVES * 2;
        uint32_t stB3 = stB1 + B_HALVES * 2;

#pragma unroll
        for (int ks = 0; ks < 2; ks++) {
            int kk = ks * 16;
            uint32_t afr[4][4];
#pragma unroll
            for (int mi = 0; mi < 4; mi++)
                ldsm4(afr[mi], stA + (uint32_t)((wm * 64 + mi * 16) * AH_STRIDE + kk) * 2 + a_lane);
            uint32_t b1f[2][4], b3f[2][4];
#pragma unroll
            for (int np = 0; np < 2; np++) {
                uint32_t ba = (uint32_t)(kk * BH_STRIDE + wn * 32 + np * 16) * 2 + b_lane;
                ldsm4t(b1f[np], stB1 + ba);
                ldsm4t(b3f[np], stB3 + ba);
            }
#pragma unroll
            for (int mi = 0; mi < 4; mi++)
#pragma unroll
                for (int np = 0; np < 2; np++) {
                    mma16(acc1[mi][np * 2],     afr[mi], &b1f[np][0]);
                    mma16(acc1[mi][np * 2 + 1], afr[mi], &b1f[np][2]);
                    mma16(acc3[mi][np * 2],     afr[mi], &b3f[np][0]);
                    mma16(acc3[mi][np * 2 + 1], afr[mi], &b3f[np][2]);
                }
        }
    }

    // epilogue: SwiGLU -> fp16 act
#pragma unroll
    for (int mi = 0; mi < 4; mi++) {
        int rA = m0 + wm * 64 + mi * 16 + fr;
        int rB = rA + 8;
#pragma unroll
        for (int ni = 0; ni < 4; ni++) {
            int col = n0 + wn * 32 + ni * 8 + fc * 2;
            if (rA < count) {
                float h0 = acc1[mi][ni][0], h1 = acc1[mi][ni][1];
                float ox = (h0 / (1.f + __expf(-h0))) * acc3[mi][ni][0];
                float oy = (h1 / (1.f + __expf(-h1))) * acc3[mi][ni][1];
                *(__half2*)(g_acth + (size_t)(off + rA) * DFF + col) = __floats2half2_rn(ox, oy);
            }
            if (rB < count) {
                float h2 = acc1[mi][ni][2], h3 = acc1[mi][ni][3];
                float ox = (h2 / (1.f + __expf(-h2))) * acc3[mi][ni][2];
                float oy = (h3 / (1.f + __expf(-h3))) * acc3[mi][ni][3];
                *(__half2*)(g_acth + (size_t)(off + rB) * DFF + col) = __floats2half2_rn(ox, oy);
            }
        }
    }
}

// ---------------- GEMM2: acth @ W2h -> weighted atomic scatter ----------------
#define G2_KC 88   // 2816/32

__global__ __launch_bounds__(256) void gemm2_mma(const __half* __restrict__ w2h,
                                                 float* __restrict__ out) {
    const int e = blockIdx.z;
    const int count = g_counts[e];
    const int m0 = blockIdx.y * 128;
    if (m0 >= count) return;
    const int n0 = blockIdx.x * 128;
    const int off = g_offsets[e];

    extern __shared__ __half dsm[];
    __shared__ int   toks[128];
    __shared__ float wts[128];

    const int tid = threadIdx.x;
    const int wid = tid >> 5;
    const int lid = tid & 31;
    const int wm = wid >> 2;
    const int wn = wid & 3;
    const int fr = lid >> 2;
    const int fc = lid & 3;
    const int l8 = lid & 7;
    const int s1 = (lid >> 3) & 1;
    const int s2 = (lid >> 4) & 1;

    if (tid < 128) {
        int r = m0 + tid;
        bool ok = r < count;
        toks[tid] = ok ? g_row_token[off + r] : 0;
        wts[tid]  = ok ? g_row_weight[off + r] : 0.f;
    }
    __syncthreads();

    const __half* W2 = w2h + (size_t)e * DFF * HID + n0;
    const uint32_t sb = s2u(dsm);
    const int arow_base = off + m0;

    const uint32_t a_lane = (uint32_t)(((l8 + s1 * 8) * AH_STRIDE + s2 * 8) * 2);
    const uint32_t b_lane = (uint32_t)(((s1 * 8 + l8) * BH_STRIDE + s2 * 8) * 2);

    auto fill = [&](int chunk, int stage) {
        uint32_t base = sb + (uint32_t)stage * G2_STG_B;
        int k0 = chunk * 32;
#pragma unroll
        for (int j = 0; j < 2; j++) {
            int i = tid + j * 256;
            int row = i >> 2, q = i & 3;
            int ridx = arow_base + row;
            if (ridx > TOTR - 1) ridx = TOTR - 1;
            cp16(base + (uint32_t)(row * AH_STRIDE + q * 8) * 2,
                 g_acth + (size_t)ridx * DFF + k0 + q * 8);
        }
        uint32_t bb = base + A_HALVES * 2;
#pragma unroll
        for (int j = 0; j < 2; j++) {
            int i = tid + j * 256;
            int k = i >> 4, q = i & 15;
            cp16(bb + (uint32_t)(k * BH_STRIDE + q * 8) * 2,
                 W2 + (size_t)(k0 + k) * HID + q * 8);
        }
        CP_COMMIT();
    };

    float acc[4][4][4];
#pragma unroll
    for (int mi = 0; mi < 4; mi++)
#pragma unroll
        for (int ni = 0; ni < 4; ni++)
#pragma unroll
            for (int v = 0; v < 4; v++) acc[mi][ni][v] = 0.f;

    fill(0, 0); fill(1, 1); fill(2, 2);

    for (int c = 0; c < G2_KC; c++) {
        if (c < G2_KC - 2)       CP_WAIT(2);
        else if (c == G2_KC - 2) CP_WAIT(1);
        else                     CP_WAIT(0);
        __syncthreads();
        if (c + 3 < G2_KC) fill(c + 3, (c + 3) & 3);

        uint32_t stA = sb + (uint32_t)(c & 3) * G2_STG_B;
        uint32_t stB = stA + A_HALVES * 2;

#pragma unroll
        for (int ks = 0; ks < 2; ks++) {
            int kk = ks * 16;
            uint32_t afr[4][4];
#pragma unroll
            for (int mi = 0; mi < 4; mi++)
                ldsm4(afr[mi], stA + (uint32_t)((wm * 64 + mi * 16) * AH_STRIDE + kk) * 2 + a_lane);
            uint32_t bf[2][4];
#pragma unroll
            for (int np = 0; np < 2; np++)
                ldsm4t(bf[np], stB + (uint32_t)(kk * BH_STRIDE + wn * 32 + np * 16) * 2 + b_lane);
#pragma unroll
            for (int mi = 0; mi < 4; mi++)
#pragma unroll
                for (int np = 0; np < 2; np++) {
                    mma16(acc[mi][np * 2],     afr[mi], &bf[np][0]);
                    mma16(acc[mi][np * 2 + 1], afr[mi], &bf[np][2]);
                }
        }
    }

#pragma unroll
    for (int mi = 0; mi < 4; mi++) {
        int mlA = wm * 64 + mi * 16 + fr;
        int mlB = mlA + 8;
        int rA = m0 + mlA, rB = m0 + mlB;
        int tkA = toks[mlA], tkB = toks[mlB];
        float wA = wts[mlA], wB = wts[mlB];
#pragma unroll
        for (int ni = 0; ni < 4; ni++) {
            int col = n0 + wn * 32 + ni * 8 + fc * 2;
            if (rA < count) {
                float* d = out + (size_t)tkA * HID + col;
                atomicAdd(d,     wA * acc[mi][ni][0]);
                atomicAdd(d + 1, wA * acc[mi][ni][1]);
            }
            if (rB < count) {
                float* d = out + (size_t)tkB * HID + col;
                atomicAdd(d,     wB * acc[mi][ni][2]);
                atomicAdd(d + 1, wB * acc[mi][ni][3]);
            }
        }
    }
}

// ---------------- aux loss ----------------
__global__ void aux_kernel(float* __restrict__ aux_out) {
    if (threadIdx.x == 0) {
        float s = 0.f;
        for (int e = 0; e < NEXP; e++) {
            float usage = (float)g_counts[e] / ((float)(T_TOK * 2) + 1e-9f);
            float imp   = g_importance[e] / (float)T_TOK;
            s += usage * imp;
        }
        float aux = s * (float)NEXP * 0.01f;
        if (aux > 1.f) aux = 1.f;
        *aux_out = aux;
    }
}

// ---------------- launch ----------------
extern "C" void kernel_launch(void* const* d_in, const int* in_sizes, int n_in,
                              void* d_out, int out_size) {
    const float* x  = (const float*)d_in[0];
    const float* gw = (const float*)d_in[1];
    const float* w1 = (const float*)d_in[2];
    const float* w3 = (const float*)d_in[3];
    const float* w2 = (const float*)d_in[4];
    float* out = (float*)d_out;

    void *p_xh, *p_w1h, *p_w3h, *p_w2h;
    cudaGetSymbolAddress(&p_xh,  g_xh);
    cudaGetSymbolAddress(&p_w1h, g_w1h);
    cudaGetSymbolAddress(&p_w3h, g_w3h);
    cudaGetSymbolAddress(&p_w2h, g_w2h);

    cudaFuncSetAttribute(gemm1_mma, cudaFuncAttributeMaxDynamicSharedMemorySize, G1_SMEM + 1024);
    cudaFuncSetAttribute(gemm2_mma, cudaFuncAttributeMaxDynamicSharedMemorySize, G2_SMEM + 1024);

    cudaMemsetAsync(out, 0, (size_t)T_TOK * HID * sizeof(float));

    // fp32 -> fp16 conversion passes
    {
        int n4x = T_TOK * HID / 4;
        cvt_fp16<<<(n4x + 255) / 256, 256>>>((const float4*)x, (__half2*)p_xh, n4x);
        int n4w = NEXP * HID * DFF / 4;
        cvt_fp16<<<(n4w + 255) / 256, 256>>>((const float4*)w1, (__half2*)p_w1h, n4w);
        cvt_fp16<<<(n4w + 255) / 256, 256>>>((const float4*)w3, (__half2*)p_w3h, n4w);
        cvt_fp16<<<(n4w + 255) / 256, 256>>>((const float4*)w2, (__half2*)p_w2h, n4w);
    }

    zero_scratch_kernel<<<1, 32>>>();
    gating_kernel<<<T_TOK, 128>>>(x, gw);
    offsets_kernel<<<1, 32>>>();
    routing_kernel<<<NEXP, 256>>>();

    dim3 g1(DFF / 128, T_TOK / 128, NEXP);   // (22, 16, 8)
    gemm1_mma<<<g1, 256, G1_SMEM + 1024>>>((const __half*)p_xh, (const __half*)p_w1h, (const __half*)p_w3h);

    dim3 g2(HID / 128, T_TOK / 128, NEXP);   // (8, 16, 8)
    gemm2_mma<<<g2, 256, G2_SMEM + 1024>>>((const __half*)p_w2h, out);

    if (out_size > T_TOK * HID) {
        aux_kernel<<<1, 32>>>(out + (size_t)T_TOK * HID);
    }
}

// round 6
// speedup vs baseline: 7.7051x; 1.0022x over previous
#include <cuda_runtime.h>
#include <cuda_fp16.h>
#include <cstdint>
#include <math.h>

#define T_TOK 2048
#define HID   1024
#define DFF   2816
#define NEXP  8
#define TOTR  4096

// ---------------- scratch ----------------
__device__ int    g_idx[T_TOK * 2];
__device__ float  g_comb[T_TOK * 2];
__device__ int    g_counts[NEXP];
__device__ int    g_offsets[NEXP];
__device__ int    g_row_token[TOTR];
__device__ float  g_row_weight[TOTR];
__device__ float  g_importance[NEXP];
__device__ __half g_xh[(size_t)T_TOK * HID];                    // 4 MB
__device__ __half g_acth[(size_t)TOTR * DFF];                   // 23 MB
__device__ __half g_w1h[(size_t)NEXP * HID * DFF];              // 46 MB [E][K=H][N=F]
__device__ __half g_w3h[(size_t)NEXP * HID * DFF];              // 46 MB
__device__ __half g_w2h[(size_t)NEXP * DFF * HID];              // 46 MB [E][K=F][N=H]

// ---------------- helpers ----------------
__device__ __forceinline__ uint32_t s2u(const void* p) {
    uint32_t a;
    asm("{ .reg .u64 t; cvta.to.shared.u64 t, %1; cvt.u32.u64 %0, t; }" : "=r"(a) : "l"(p));
    return a;
}
__device__ __forceinline__ void cp16(uint32_t s, const void* g) {
    asm volatile("cp.async.cg.shared.global [%0], [%1], 16;" :: "r"(s), "l"(g));
}
#define CP_COMMIT() asm volatile("cp.async.commit_group;" ::: "memory")
#define CP_WAIT(n)  asm volatile("cp.async.wait_group %0;" :: "n"(n) : "memory")

__device__ __forceinline__ void ldsm4(uint32_t* r, uint32_t a) {
    asm volatile("ldmatrix.sync.aligned.m8n8.x4.shared.b16 {%0,%1,%2,%3}, [%4];"
                 : "=r"(r[0]), "=r"(r[1]), "=r"(r[2]), "=r"(r[3]) : "r"(a));
}
__device__ __forceinline__ void ldsm4t(uint32_t* r, uint32_t a) {
    asm volatile("ldmatrix.sync.aligned.m8n8.x4.trans.shared.b16 {%0,%1,%2,%3}, [%4];"
                 : "=r"(r[0]), "=r"(r[1]), "=r"(r[2]), "=r"(r[3]) : "r"(a));
}
__device__ __forceinline__ void mma16(float* d, const uint32_t* a, const uint32_t* b) {
    asm volatile(
        "mma.sync.aligned.m16n8k16.row.col.f32.f16.f16.f32 "
        "{%0,%1,%2,%3}, {%4,%5,%6,%7}, {%8,%9}, {%0,%1,%2,%3};"
        : "+f"(d[0]), "+f"(d[1]), "+f"(d[2]), "+f"(d[3])
        : "r"(a[0]), "r"(a[1]), "r"(a[2]), "r"(a[3]), "r"(b[0]), "r"(b[1]));
}

// smem geometry (halves)
#define AH_STRIDE 40
#define BH_STRIDE 136
#define A_HALVES (128 * AH_STRIDE)
#define B_HALVES (32 * BH_STRIDE)
#define G1_STG_B (A_HALVES * 2 + B_HALVES * 2 * 2)   // 27648 B
#define G2_STG_B (A_HALVES * 2 + B_HALVES * 2)       // 18944 B
#define NSTAGE 4
#define G1_SMEM (NSTAGE * G1_STG_B)
#define G2_SMEM (NSTAGE * G2_STG_B)

// ---------------- fp32 -> fp16 converts ----------------
__global__ void cvt_fp16(const float4* __restrict__ src, __half2* __restrict__ dst, int n4) {
    int i = blockIdx.x * blockDim.x + threadIdx.x;
    if (i < n4) {
        float4 v = src[i];
        dst[2 * i]     = __floats2half2_rn(v.x, v.y);
        dst[2 * i + 1] = __floats2half2_rn(v.z, v.w);
    }
}
// three weight tensors in one launch (z selects tensor)
__global__ void cvt_fp16_w(const float4* __restrict__ wA, __half2* __restrict__ dA,
                           const float4* __restrict__ wB, __half2* __restrict__ dB,
                           int n4) {
    int i = blockIdx.x * blockDim.x + threadIdx.x;
    if (i >= n4) return;
    const float4* s = blockIdx.z ? wB : wA;
    __half2* d = blockIdx.z ? dB : dA;
    float4 v = s[i];
    d[2 * i]     = __floats2half2_rn(v.x, v.y);
    d[2 * i + 1] = __floats2half2_rn(v.z, v.w);
}

// ---------------- zero / gating (warp-per-token) / offsets / routing ----------------
__global__ void zero_scratch_kernel() {
    int t = threadIdx.x;
    if (t < NEXP) { g_counts[t] = 0; g_importance[t] = 0.f; }
}

__global__ void gating_kernel(const float* __restrict__ x,
                              const float* __restrict__ gw) {
    int warp = (blockIdx.x * blockDim.x + threadIdx.x) >> 5;   // token
    int lid  = threadIdx.x & 31;
    if (warp >= T_TOK) return;
    const float4* xr = (const float4*)(x + (size_t)warp * HID);

    float p[NEXP];
#pragma unroll
    for (int e = 0; e < NEXP; e++) p[e] = 0.f;
#pragma unroll
    for (int q = 0; q < 8; q++) {
        int idx = q * 32 + lid;          // float4 index within row
        float4 xv = xr[idx];
#pragma unroll
        for (int e = 0; e < NEXP; e++) {
            float4 gv = ((const float4*)(gw + e * HID))[idx];
            p[e] += xv.x * gv.x + xv.y * gv.y + xv.z * gv.z + xv.w * gv.w;
        }
    }
#pragma unroll
    for (int e = 0; e < NEXP; e++) {
#pragma unroll
        for (int o = 16; o > 0; o >>= 1)
            p[e] += __shfl_xor_sync(0xFFFFFFFFu, p[e], o);
    }

    if (lid == 0) {
        int t = warp;
        int i0 = 0;
#pragma unroll
        for (int e = 1; e < NEXP; e++) if (p[e] > p[i0]) i0 = e;
        int i1 = -1;
#pragma unroll
        for (int e = 0; e < NEXP; e++) {
            if (e == i0) continue;
            if (i1 < 0 || p[e] > p[i1]) i1 = e;
        }
        float m = p[i0];
        float e1 = expf(p[i1] - m);
        float inv = 1.f / (1.f + e1);
        g_idx[t * 2]      = i0;
        g_idx[t * 2 + 1]  = i1;
        g_comb[t * 2]     = inv;
        g_comb[t * 2 + 1] = e1 * inv;
        atomicAdd(&g_counts[i0], 1);
        atomicAdd(&g_counts[i1], 1);

        float se = 0.f, pe[NEXP];
#pragma unroll
        for (int e = 0; e < NEXP; e++) { pe[e] = expf(p[e] - m); se += pe[e]; }
        float isum = 1.f / se;
#pragma unroll
        for (int e = 0; e < NEXP; e++) atomicAdd(&g_importance[e], pe[e] * isum);
    }
}

__global__ void offsets_kernel() {
    if (threadIdx.x == 0) {
        int cum = 0;
        for (int e = 0; e < NEXP; e++) { g_offsets[e] = cum; cum += g_counts[e]; }
    }
}

__global__ void routing_kernel() {
    int e = blockIdx.x;
    int tid = threadIdx.x;
    __shared__ int scan[256];
    __shared__ int base;
    if (tid == 0) base = g_offsets[e];
    __syncthreads();

    for (int t0 = 0; t0 < T_TOK; t0 += 256) {
        int t = t0 + tid;
        int sel = 0; float w = 0.f;
        if (g_idx[2 * t] == e)          { sel = 1; w = g_comb[2 * t]; }
        else if (g_idx[2 * t + 1] == e) { sel = 1; w = g_comb[2 * t + 1]; }
        scan[tid] = sel;
        __syncthreads();
        for (int ofs = 1; ofs < 256; ofs <<= 1) {
            int v = 0;
            if (tid >= ofs) v = scan[tid - ofs];
            __syncthreads();
            if (tid >= ofs) scan[tid] += v;
            __syncthreads();
        }
        if (sel) {
            int pos = base + scan[tid] - 1;
            g_row_token[pos]  = t;
            g_row_weight[pos] = w;
        }
        __syncthreads();
        if (tid == 0) base += scan[255];
        __syncthreads();
    }
}

// ---------------- GEMM1 ----------------
#define G1_KC 32

__global__ __launch_bounds__(256) void gemm1_mma(const __half* __restrict__ xh,
                                                 const __half* __restrict__ w1h,
                                                 const __half* __restrict__ w3h) {
    const int e = blockIdx.z;
    const int count = g_counts[e];
    const int m0 = blockIdx.y * 128;
    if (m0 >= count) return;
    const int n0 = blockIdx.x * 128;
    const int off = g_offsets[e];

    extern __shared__ __half dsm[];
    __shared__ int toks[128];

    const int tid = threadIdx.x;
    const int wid = tid >> 5;
    const int lid = tid & 31;
    const int wm = wid >> 2;
    const int wn = wid & 3;
    const int fr = lid >> 2;
    const int fc = lid & 3;
    const int l8 = lid & 7;
    const int s1 = (lid >> 3) & 1;
    const int s2 = (lid >> 4) & 1;

    if (tid < 128) {
        int r = m0 + tid;
        toks[tid] = (r < count) ? g_row_token[off + r] : 0;
    }
    __syncthreads();

    const __half* W1 = w1h + (size_t)e * HID * DFF + n0;
    const __half* W3 = w3h + (size_t)e * HID * DFF + n0;
    const uint32_t sb = s2u(dsm);

    const uint32_t a_lane = (uint32_t)(((l8 + s1 * 8) * AH_STRIDE + s2 * 8) * 2);
    const uint32_t b_lane = (uint32_t)(((s1 * 8 + l8) * BH_STRIDE + s2 * 8) * 2);

    auto fill = [&](int chunk, int stage) {
        uint32_t base = sb + (uint32_t)stage * G1_STG_B;
        int k0 = chunk * 32;
#pragma unroll
        for (int j = 0; j < 2; j++) {
            int i = tid + j * 256;
            int row = i >> 2, q = i & 3;
            cp16(base + (uint32_t)(row * AH_STRIDE + q * 8) * 2,
                 xh + (size_t)toks[row] * HID + k0 + q * 8);
        }
        uint32_t bb = base + A_HALVES * 2;
#pragma unroll
        for (int j = 0; j < 2; j++) {
            int i = tid + j * 256;
            int k = i >> 4, q = i & 15;
            uint32_t o = (uint32_t)(k * BH_STRIDE + q * 8) * 2;
            cp16(bb + o,                W1 + (size_t)(k0 + k) * DFF + q * 8);
            cp16(bb + B_HALVES * 2 + o, W3 + (size_t)(k0 + k) * DFF + q * 8);
        }
        CP_COMMIT();
    };

    float acc1[4][4][4], acc3[4][4][4];
#pragma unroll
    for (int mi = 0; mi < 4; mi++)
#pragma unroll
        for (int ni = 0; ni < 4; ni++)
#pragma unroll
            for (int v = 0; v < 4; v++) { acc1[mi][ni][v] = 0.f; acc3[mi][ni][v] = 0.f; }

    fill(0, 0); fill(1, 1); fill(2, 2);

    for (int c = 0; c < G1_KC; c++) {
        if (c < G1_KC - 2)       CP_WAIT(2);
        else if (c == G1_KC - 2) CP_WAIT(1);
        else                     CP_WAIT(0);
        __syncthreads();
        if (c + 3 < G1_KC) fill(c + 3, (c + 3) & 3);

        uint32_t stA  = sb + (uint32_t)(c & 3) * G1_STG_B;
        uint32_t stB1 = stA + A_HALVES * 2;
        uint32_t stB3 = stB1 + B_HALVES * 2;

#pragma unroll
        for (int ks = 0; ks < 2; ks++) {
            int kk = ks * 16;
            uint32_t afr[4][4];
#pragma unroll
            for (int mi = 0; mi < 4; mi++)
                ldsm4(afr[mi], stA + (uint32_t)((wm * 64 + mi * 16) * AH_STRIDE + kk) * 2 + a_lane);
            uint32_t b1f[2][4], b3f[2][4];
#pragma unroll
            for (int np = 0; np < 2; np++) {
                uint32_t ba = (uint32_t)(kk * BH_STRIDE + wn * 32 + np * 16) * 2 + b_lane;
                ldsm4t(b1f[np], stB1 + ba);
                ldsm4t(b3f[np], stB3 + ba);
            }
#pragma unroll
            for (int mi = 0; mi < 4; mi++)
#pragma unroll
                for (int np = 0; np < 2; np++) {
                    mma16(acc1[mi][np * 2],     afr[mi], &b1f[np][0]);
                    mma16(acc1[mi][np * 2 + 1], afr[mi], &b1f[np][2]);
                    mma16(acc3[mi][np * 2],     afr[mi], &b3f[np][0]);
                    mma16(acc3[mi][np * 2 + 1], afr[mi], &b3f[np][2]);
                }
        }
    }

#pragma unroll
    for (int mi = 0; mi < 4; mi++) {
        int rA = m0 + wm * 64 + mi * 16 + fr;
        int rB = rA + 8;
#pragma unroll
        for (int ni = 0; ni < 4; ni++) {
            int col = n0 + wn * 32 + ni * 8 + fc * 2;
            if (rA < count) {
                float h0 = acc1[mi][ni][0], h1 = acc1[mi][ni][1];
                float ox = (h0 / (1.f + __expf(-h0))) * acc3[mi][ni][0];
                float oy = (h1 / (1.f + __expf(-h1))) * acc3[mi][ni][1];
                *(__half2*)(g_acth + (size_t)(off + rA) * DFF + col) = __floats2half2_rn(ox, oy);
            }
            if (rB < count) {
                float h2 = acc1[mi][ni][2], h3 = acc1[mi][ni][3];
                float ox = (h2 / (1.f + __expf(-h2))) * acc3[mi][ni][2];
                float oy = (h3 / (1.f + __expf(-h3))) * acc3[mi][ni][3];
                *(__half2*)(g_acth + (size_t)(off + rB) * DFF + col) = __floats2half2_rn(ox, oy);
            }
        }
    }
}

// ---------------- GEMM2 ----------------
#define G2_KC 88

__global__ __launch_bounds__(256) void gemm2_mma(const __half* __restrict__ w2h,
                                                 float* __restrict__ out) {
    const int e = blockIdx.z;
    const int count = g_counts[e];
    const int m0 = blockIdx.y * 128;
    if (m0 >= count) return;
    const int n0 = blockIdx.x * 128;
    const int off = g_offsets[e];

    extern __shared__ __half dsm[];
    __shared__ int   toks[128];
    __shared__ float wts[128];

    const int tid = threadIdx.x;
    const int wid = tid >> 5;
    const int lid = tid & 31;
    const int wm = wid >> 2;
    const int wn = wid & 3;
    const int fr = lid >> 2;
    const int fc = lid & 3;
    const int l8 = lid & 7;
    const int s1 = (lid >> 3) & 1;
    const int s2 = (lid >> 4) & 1;

    if (tid < 128) {
        int r = m0 + tid;
        bool ok = r < count;
        toks[tid] = ok ? g_row_token[off + r] : 0;
        wts[tid]  = ok ? g_row_weight[off + r] : 0.f;
    }
    __syncthreads();

    const __half* W2 = w2h + (size_t)e * DFF * HID + n0;
    const uint32_t sb = s2u(dsm);
    const int arow_base = off + m0;

    const uint32_t a_lane = (uint32_t)(((l8 + s1 * 8) * AH_STRIDE + s2 * 8) * 2);
    const uint32_t b_lane = (uint32_t)(((s1 * 8 + l8) * BH_STRIDE + s2 * 8) * 2);

    auto fill = [&](int chunk, int stage) {
        uint32_t base = sb + (uint32_t)stage * G2_STG_B;
        int k0 = chunk * 32;
#pragma unroll
        for (int j = 0; j < 2; j++) {
            int i = tid + j * 256;
            int row = i >> 2, q = i & 3;
            int ridx = arow_base + row;
            if (ridx > TOTR - 1) ridx = TOTR - 1;
            cp16(base + (uint32_t)(row * AH_STRIDE + q * 8) * 2,
                 g_acth + (size_t)ridx * DFF + k0 + q * 8);
        }
        uint32_t bb = base + A_HALVES * 2;
#pragma unroll
        for (int j = 0; j < 2; j++) {
            int i = tid + j * 256;
            int k = i >> 4, q = i & 15;
            cp16(bb + (uint32_t)(k * BH_STRIDE + q * 8) * 2,
                 W2 + (size_t)(k0 + k) * HID + q * 8);
        }
        CP_COMMIT();
    };

    float acc[4][4][4];
#pragma unroll
    for (int mi = 0; mi < 4; mi++)
#pragma unroll
        for (int ni = 0; ni < 4; ni++)
#pragma unroll
            for (int v = 0; v < 4; v++) acc[mi][ni][v] = 0.f;

    fill(0, 0); fill(1, 1); fill(2, 2);

    for (int c = 0; c < G2_KC; c++) {
        if (c < G2_KC - 2)       CP_WAIT(2);
        else if (c == G2_KC - 2) CP_WAIT(1);
        else                     CP_WAIT(0);
        __syncthreads();
        if (c + 3 < G2_KC) fill(c + 3, (c + 3) & 3);

        uint32_t stA = sb + (uint32_t)(c & 3) * G2_STG_B;
        uint32_t stB = stA + A_HALVES * 2;

#pragma unroll
        for (int ks = 0; ks < 2; ks++) {
            int kk = ks * 16;
            uint32_t afr[4][4];
#pragma unroll
            for (int mi = 0; mi < 4; mi++)
                ldsm4(afr[mi], stA + (uint32_t)((wm * 64 + mi * 16) * AH_STRIDE + kk) * 2 + a_lane);
            uint32_t bf[2][4];
#pragma unroll
            for (int np = 0; np < 2; np++)
                ldsm4t(bf[np], stB + (uint32_t)(kk * BH_STRIDE + wn * 32 + np * 16) * 2 + b_lane);
#pragma unroll
            for (int mi = 0; mi < 4; mi++)
#pragma unroll
                for (int np = 0; np < 2; np++) {
                    mma16(acc[mi][np * 2],     afr[mi], &bf[np][0]);
                    mma16(acc[mi][np * 2 + 1], afr[mi], &bf[np][2]);
                }
        }
    }

#pragma unroll
    for (int mi = 0; mi < 4; mi++) {
        int mlA = wm * 64 + mi * 16 + fr;
        int mlB = mlA + 8;
        int rA = m0 + mlA, rB = m0 + mlB;
        int tkA = toks[mlA], tkB = toks[mlB];
        float wA = wts[mlA], wB = wts[mlB];
#pragma unroll
        for (int ni = 0; ni < 4; ni++) {
            int col = n0 + wn * 32 + ni * 8 + fc * 2;
            if (rA < count) {
                float* d = out + (size_t)tkA * HID + col;
                atomicAdd(d,     wA * acc[mi][ni][0]);
                atomicAdd(d + 1, wA * acc[mi][ni][1]);
            }
            if (rB < count) {
                float* d = out + (size_t)tkB * HID + col;
                atomicAdd(d,     wB * acc[mi][ni][2]);
                atomicAdd(d + 1, wB * acc[mi][ni][3]);
            }
        }
    }
}

// ---------------- aux loss ----------------
__global__ void aux_kernel(float* __restrict__ aux_out) {
    if (threadIdx.x == 0) {
        float s = 0.f;
        for (int e = 0; e < NEXP; e++) {
            float usage = (float)g_counts[e] / ((float)(T_TOK * 2) + 1e-9f);
            float imp   = g_importance[e] / (float)T_TOK;
            s += usage * imp;
        }
        float aux = s * (float)NEXP * 0.01f;
        if (aux > 1.f) aux = 1.f;
        *aux_out = aux;
    }
}

// ---------------- launch ----------------
extern "C" void kernel_launch(void* const* d_in, const int* in_sizes, int n_in,
                              void* d_out, int out_size) {
    const float* x  = (const float*)d_in[0];
    const float* gw = (const float*)d_in[1];
    const float* w1 = (const float*)d_in[2];
    const float* w3 = (const float*)d_in[3];
    const float* w2 = (const float*)d_in[4];
    float* out = (float*)d_out;

    void *p_xh, *p_w1h, *p_w3h, *p_w2h;
    cudaGetSymbolAddress(&p_xh,  g_xh);
    cudaGetSymbolAddress(&p_w1h, g_w1h);
    cudaGetSymbolAddress(&p_w3h, g_w3h);
    cudaGetSymbolAddress(&p_w2h, g_w2h);

    // persistent side streams/events (created once, outside capture on the
    // correctness call; graph content is identical every call)
    static cudaStream_t sB = nullptr, sC = nullptr;
    static cudaEvent_t evFork = nullptr, evB = nullptr, evC = nullptr;
    static bool inited = false;
    if (!inited) {
        cudaStreamCreateWithFlags(&sB, cudaStreamNonBlocking);
        cudaStreamCreateWithFlags(&sC, cudaStreamNonBlocking);
        cudaEventCreateWithFlags(&evFork, cudaEventDisableTiming);
        cudaEventCreateWithFlags(&evB, cudaEventDisableTiming);
        cudaEventCreateWithFlags(&evC, cudaEventDisableTiming);
        cudaFuncSetAttribute(gemm1_mma, cudaFuncAttributeMaxDynamicSharedMemorySize, G1_SMEM + 1024);
        cudaFuncSetAttribute(gemm2_mma, cudaFuncAttributeMaxDynamicSharedMemorySize, G2_SMEM + 1024);
        inited = true;
    }

    const int n4w = NEXP * HID * DFF / 4;
    const int n4x = T_TOK * HID / 4;

    // fork
    cudaEventRecord(evFork, 0);
    cudaStreamWaitEvent(sB, evFork, 0);
    cudaStreamWaitEvent(sC, evFork, 0);

    // branch A (main stream): w1 + w3 converts (needed by gemm1)
    {
        dim3 g((n4w + 255) / 256, 1, 2);
        cvt_fp16_w<<<g, 256>>>((const float4*)w1, (__half2*)p_w1h,
                               (const float4*)w3, (__half2*)p_w3h, n4w);
    }

    // branch B: routing chain + x convert + aux prereqs
    zero_scratch_kernel<<<1, 32, 0, sB>>>();
    gating_kernel<<<T_TOK / 8, 256, 0, sB>>>(x, gw);
    offsets_kernel<<<1, 32, 0, sB>>>();
    routing_kernel<<<NEXP, 256, 0, sB>>>();
    cvt_fp16<<<(n4x + 255) / 256, 256, 0, sB>>>((const float4*)x, (__half2*)p_xh, n4x);
    cudaEventRecord(evB, sB);

    // branch C: w2 convert + output zero (needed by gemm2)
    cvt_fp16<<<(n4w + 255) / 256, 256, 0, sC>>>((const float4*)w2, (__half2*)p_w2h, n4w);
    cudaMemsetAsync(out, 0, (size_t)T_TOK * HID * sizeof(float), sC);
    cudaEventRecord(evC, sC);

    // join B into main, run gemm1
    cudaStreamWaitEvent(0, evB, 0);
    dim3 g1(DFF / 128, T_TOK / 128, NEXP);
    gemm1_mma<<<g1, 256, G1_SMEM + 1024>>>((const __half*)p_xh, (const __half*)p_w1h, (const __half*)p_w3h);

    // join C, run gemm2
    cudaStreamWaitEvent(0, evC, 0);
    dim3 g2(HID / 128, T_TOK / 128, NEXP);
    gemm2_mma<<<g2, 256, G2_SMEM + 1024>>>((const __half*)p_w2h, out);

    if (out_size > T_TOK * HID) {
        aux_kernel<<<1, 32>>>(out + (size_t)T_TOK * HID);
    }
}